// round 4
// baseline (speedup 1.0000x reference)
#include <cuda_runtime.h>

// SubGraphAvgPool: out[b,g,d] = mean(h[b,g,d], h[b,4g+1..4g+4,d]),  B=16, N=8193, D=512, G=2048.
//
// One CTA per (b, g-pair): g0=2*gi, g1=2*gi+1. Children of the pair are rows
// 8gi+1..8gi+8 (contiguous 16KB); g-rows 2gi,2gi+1 (contiguous, L2 hits).
// 128 threads, one float4 column slice per thread, 10 independent LDG.128
// front-batched (MLP=10) + 2 STG.128.
//
// Cache hints: child rows streaming (__ldcs) when they're >= 2049 (single-use),
// default otherwise (re-read later as g-rows); g-rows __ldcs (last use);
// output __stcs (never re-read).

static constexpr int B = 16;
static constexpr long long N = 8193;
static constexpr int D = 512;
static constexpr int G = 2048;
static constexpr int DV = D / 4;   // 128 float4 per row
static constexpr int GP = G / 2;   // 1024 g-pairs per batch

__global__ __launch_bounds__(128)
void subgraph_avgpool_kernel(const float* __restrict__ h, float* __restrict__ out) {
    const int blk = blockIdx.x;         // 0 .. B*GP-1
    const int gi  = blk & (GP - 1);     // GP = 1024 = 2^10
    const int b   = blk >> 10;
    const int dv  = threadIdx.x;        // 0 .. 127

    const float4* __restrict__ hp =
        reinterpret_cast<const float4*>(h) + (long long)b * (N * DV) + dv;

    // g-rows 2gi, 2gi+1: last use (already in L2 from earlier child reads)
    const float4* gp = hp + (long long)(2 * gi) * DV;
    const float4 q0 = __ldcs(gp);
    const float4 q1 = __ldcs(gp + DV);

    // child rows 8gi+1 .. 8gi+8: contiguous
    const float4* p = hp + (long long)(8 * gi + 1) * DV;
    float4 c0, c1, c2, c3, c4, c5, c6, c7;
    if (gi >= 256) {
        // rows >= 2049: single-use stream, evict-first
        c0 = __ldcs(p);          c1 = __ldcs(p + DV);
        c2 = __ldcs(p + 2 * DV); c3 = __ldcs(p + 3 * DV);
        c4 = __ldcs(p + 4 * DV); c5 = __ldcs(p + 5 * DV);
        c6 = __ldcs(p + 6 * DV); c7 = __ldcs(p + 7 * DV);
    } else {
        // rows 1..2048: re-read later as g-rows -> keep in L2
        c0 = __ldg(p);           c1 = __ldg(p + DV);
        c2 = __ldg(p + 2 * DV);  c3 = __ldg(p + 3 * DV);
        c4 = __ldg(p + 4 * DV);  c5 = __ldg(p + 5 * DV);
        c6 = __ldg(p + 6 * DV);  c7 = __ldg(p + 7 * DV);
    }

    float4 s0, s1;
    s0.x = (q0.x + c0.x + c1.x + c2.x + c3.x) * 0.2f;
    s0.y = (q0.y + c0.y + c1.y + c2.y + c3.y) * 0.2f;
    s0.z = (q0.z + c0.z + c1.z + c2.z + c3.z) * 0.2f;
    s0.w = (q0.w + c0.w + c1.w + c2.w + c3.w) * 0.2f;

    s1.x = (q1.x + c4.x + c5.x + c6.x + c7.x) * 0.2f;
    s1.y = (q1.y + c4.y + c5.y + c6.y + c7.y) * 0.2f;
    s1.z = (q1.z + c4.z + c5.z + c6.z + c7.z) * 0.2f;
    s1.w = (q1.w + c4.w + c5.w + c6.w + c7.w) * 0.2f;

    float4* op = reinterpret_cast<float4*>(out) + ((long long)b * G + 2 * gi) * DV + dv;
    __stcs(op, s0);
    __stcs(op + DV, s1);
}

extern "C" void kernel_launch(void* const* d_in, const int* in_sizes, int n_in,
                              void* d_out, int out_size) {
    const float* h = (const float*)d_in[0];
    float* out = (float*)d_out;
    subgraph_avgpool_kernel<<<B * GP, 128>>>(h, out);
}